// round 7
// baseline (speedup 1.0000x reference)
#include <cuda_runtime.h>
#include <mma.h>
#include <math.h>
#include <stdint.h>

using namespace nvcuda;

#define Bn 4
#define Tn 2048
#define Dn 1024
#define Hn 16
#define HDn 64
#define MROWS (Bn*Tn)      // 8192
#define QKVN (3*Dn)        // 3072

__device__ float g_qkv[(size_t)MROWS * QKVN];
__device__ float g_attn[(size_t)MROWS * Dn];
__device__ float g_xr[(size_t)MROWS * Dn];
__device__ float g_wq[(size_t)Dn * QKVN];
__device__ float g_wo[(size_t)Dn * Dn];

__device__ __forceinline__ float to_tf32(float x) {
    uint32_t u;
    asm("cvt.rna.tf32.f32 %0, %1;" : "=r"(u) : "f"(x));
    return __uint_as_float(u);
}
__device__ __forceinline__ uint32_t s2u(const void* p) {
    return (uint32_t)__cvta_generic_to_shared(p);
}
__device__ __forceinline__ void cp16(uint32_t dst, const void* src) {
    asm volatile("cp.async.cg.shared.global [%0], [%1], 16;" :: "r"(dst), "l"(src));
}
__device__ __forceinline__ void cp_commit() { asm volatile("cp.async.commit_group;"); }
__device__ __forceinline__ void cp_wait0()  { asm volatile("cp.async.wait_group 0;"); }

__global__ void __launch_bounds__(256) preround_kernel(
    const float* __restrict__ src, float* __restrict__ dst, int total4)
{
    int idx = blockIdx.x * blockDim.x + threadIdx.x;
    if (idx >= total4) return;
    float4 v = *(const float4*)&src[idx * 4];
    v.x = to_tf32(v.x); v.y = to_tf32(v.y);
    v.z = to_tf32(v.z); v.w = to_tf32(v.w);
    *(float4*)&dst[idx * 4] = v;
}

// ---------------------------------------------------------------------------
// TF32 GEMM: 128x128 tile, BK=32, cp.async double buffer. Inputs pre-rounded.
// ---------------------------------------------------------------------------
#define AP_A 36
#define AP_B 132
#define A_STG (128*AP_A)
#define B_STG (32*AP_B)
#define GEMM_SMEM ((2*A_STG + 2*B_STG) * 4)

template <int ROUND_OUT>
__global__ void __launch_bounds__(256, 2) gemm_tf32_v3(
    const float* __restrict__ A, const float* __restrict__ Bm,
    float* __restrict__ C, int M, int N, int K)
{
    extern __shared__ float sm[];
    float* As = sm;
    float* Bs = sm + 2*A_STG;

    const int tid = threadIdx.x;
    const int bm = blockIdx.y * 128;
    const int bn = blockIdx.x * 128;
    const int w  = tid >> 5;
    const int wm = (w >> 2) * 64;
    const int wn = (w & 3) * 32;

    wmma::fragment<wmma::accumulator, 16, 16, 8, float> acc[4][2];
    #pragma unroll
    for (int i = 0; i < 4; i++)
        #pragma unroll
        for (int j = 0; j < 2; j++) wmma::fill_fragment(acc[i][j], 0.f);

    const int nk = K / 32;

    auto prefetch = [&](int kt, int stg) {
        const int k0 = kt * 32;
        float* ad = As + stg * A_STG;
        float* bd = Bs + stg * B_STG;
        #pragma unroll
        for (int i = 0; i < 4; i++) {
            int id = tid + 256*i;
            int r = id >> 3, c = (id & 7) * 4;
            cp16(s2u(ad + r*AP_A + c), &A[(size_t)(bm + r) * K + k0 + c]);
        }
        #pragma unroll
        for (int i = 0; i < 4; i++) {
            int id = tid + 256*i;
            int r = id >> 5, c = (id & 31) * 4;
            cp16(s2u(bd + r*AP_B + c), &Bm[(size_t)(k0 + r) * N + bn + c]);
        }
        cp_commit();
    };

    prefetch(0, 0);
    int stg = 0;

    for (int kt = 0; kt < nk; kt++) {
        cp_wait0();
        __syncthreads();
        if (kt + 1 < nk) prefetch(kt + 1, stg ^ 1);

        const float* a0 = As + stg * A_STG;
        const float* b0 = Bs + stg * B_STG;
        #pragma unroll
        for (int kk = 0; kk < 4; kk++) {
            wmma::fragment<wmma::matrix_a, 16, 16, 8, wmma::precision::tf32, wmma::row_major> af[4];
            wmma::fragment<wmma::matrix_b, 16, 16, 8, wmma::precision::tf32, wmma::row_major> bf[2];
            #pragma unroll
            for (int i = 0; i < 4; i++)
                wmma::load_matrix_sync(af[i], a0 + (wm + i*16)*AP_A + kk*8, AP_A);
            #pragma unroll
            for (int j = 0; j < 2; j++)
                wmma::load_matrix_sync(bf[j], b0 + (kk*8)*AP_B + wn + j*16, AP_B);
            #pragma unroll
            for (int i = 0; i < 4; i++)
                #pragma unroll
                for (int j = 0; j < 2; j++)
                    wmma::mma_sync(acc[i][j], af[i], bf[j], acc[i][j]);
        }
        stg ^= 1;
        __syncthreads();
    }

    #pragma unroll
    for (int i = 0; i < 4; i++)
        #pragma unroll
        for (int j = 0; j < 2; j++) {
            if (ROUND_OUT) {
                #pragma unroll
                for (int t = 0; t < acc[i][j].num_elements; t++)
                    acc[i][j].x[t] = to_tf32(acc[i][j].x[t]);
            }
            wmma::store_matrix_sync(&C[(size_t)(bm + wm + i*16) * N + bn + wn + j*16],
                                    acc[i][j], N, wmma::mem_row_major);
        }
}

__global__ void __launch_bounds__(256) bias_add_kernel(
    float* __restrict__ out, const float* __restrict__ bias, int total4, int N)
{
    int idx = blockIdx.x * blockDim.x + threadIdx.x;
    if (idx >= total4) return;
    int col = (idx * 4) & (N - 1);
    float4 v = *(float4*)&out[idx * 4];
    v.x += bias[col+0]; v.y += bias[col+1];
    v.z += bias[col+2]; v.w += bias[col+3];
    *(float4*)&out[idx * 4] = v;
}

// ---------------------------------------------------------------------------
// RoPE + L2 norm, writes tf32-rounded q,k in place.
// ---------------------------------------------------------------------------
__global__ void __launch_bounds__(256) rope_norm_kernel(float* __restrict__ qkv)
{
    const int gw = (blockIdx.x * blockDim.x + threadIdx.x) >> 5;
    const int lane = threadIdx.x & 31;
    const int which = gw & 1;
    const int h = (gw >> 1) & (Hn - 1);
    const int t = (gw >> 5) & (Tn - 1);
    const int b = gw >> 16;

    float* p = qkv + (size_t)(b*Tn + t) * QKVN + which*Dn + h*HDn;

    const float inv_freq = powf(10000.f, -(float)lane * (1.f/32.f));
    const float ang = (float)t * inv_freq;
    float s, c;
    sincosf(ang, &s, &c);

    const float x1 = p[lane];
    const float x2 = p[lane + 32];
    const float r1 = x1*c - x2*s;
    const float r2 = x1*s + x2*c;

    float ss = r1*r1 + r2*r2;
    #pragma unroll
    for (int off = 16; off; off >>= 1)
        ss += __shfl_xor_sync(0xffffffffu, ss, off);

    const float inv = rsqrtf(ss + 1e-6f);
    p[lane]      = to_tf32(r1 * inv);
    p[lane + 32] = to_tf32(r2 * inv);
}

// ---------------------------------------------------------------------------
// TF32 flash attention v3: 64 q-rows, 256 threads / 8 warps.
// Warp w: q-rows (w&3)*16, key-half (w>>2)*32. exp on accumulator registers.
// Partial O per key-half; reduced through (reused) K buffer at the end.
// q,k unit vectors -> |score|<=0.125 -> exp without max/rescale.
// ---------------------------------------------------------------------------
#define AP 72
#define KV_STG (64*AP)
#define ATT_SMEM ((64*AP + 2*KV_STG + 2*KV_STG + 64*AP + 64) * 4)

__global__ void __launch_bounds__(256, 2) attn_tc_kernel(
    const float* __restrict__ qkv, float* __restrict__ outp)
{
    extern __shared__ float sm[];
    float* Qs   = sm;                        // 64 x AP (tf32)
    float* Ks   = Qs + 64*AP;                // 2 x 64 x AP (also O-partials at end)
    float* Vs   = Ks + 2*KV_STG;             // 2 x 64 x AP
    float* Ps   = Vs + 2*KV_STG;             // 64 x AP
    float* lrow = Ps + 64*AP;                // 64

    const int tid  = threadIdx.x;
    const int w    = tid >> 5;               // 0..7
    const int lane = tid & 31;
    const int qw   = w & 3;                  // q-row group
    const int kh   = w >> 2;                 // key half 0/1
    const int rowm = qw * 16;
    const int kcol = kh * 32;

    const int qt = blockIdx.x & 31;
    const int h  = (blockIdx.x >> 5) & (Hn-1);
    const int b  = blockIdx.x >> 9;
    const int q0 = qt * 64;

    const float* qbase = qkv + (size_t)(b*Tn) * QKVN + h*HDn;
    const float* kbase = qbase + Dn;
    const float* vbase = qbase + 2*Dn;

    auto prefetch_kv = [&](int kt, int stg) {
        float* kd = Ks + stg*KV_STG;
        float* vd = Vs + stg*KV_STG;
        #pragma unroll
        for (int i = 0; i < 4; i++) {
            int id = tid + 256*i;
            int r = id >> 4, c = (id & 15) * 4;
            cp16(s2u(kd + r*AP + c), kbase + (size_t)(kt*64 + r) * QKVN + c);
        }
        #pragma unroll
        for (int i = 0; i < 4; i++) {
            int id = tid + 256*i;
            int r = id >> 4, c = (id & 15) * 4;
            cp16(s2u(vd + r*AP + c), vbase + (size_t)(kt*64 + r) * QKVN + c);
        }
        cp_commit();
    };

    prefetch_kv(0, 0);

    // Q tile: scale by 1/8 (power of two => stays tf32)
    {
        const int r  = tid >> 2;
        const int c0 = (tid & 3) * 16;
        const float* src = qbase + (size_t)(q0 + r) * QKVN + c0;
        float* dst = Qs + r*AP + c0;
        #pragma unroll
        for (int j = 0; j < 4; j++) {
            float4 v = *(const float4*)(src + j*4);
            dst[j*4+0] = 0.125f * v.x;
            dst[j*4+1] = 0.125f * v.y;
            dst[j*4+2] = 0.125f * v.z;
            dst[j*4+3] = 0.125f * v.w;
        }
    }
    if (tid < 64) lrow[tid] = 0.f;

    wmma::fragment<wmma::accumulator, 16, 16, 8, float> oacc[4];
    #pragma unroll
    for (int j = 0; j < 4; j++) wmma::fill_fragment(oacc[j], 0.f);

    int stg = 0;

    for (int kt = 0; kt < Tn/64; kt++) {
        cp_wait0();
        __syncthreads();   // KV tile ready; all warps done with prior PV

        const float* kc = Ks + stg*KV_STG;
        const float* vc = Vs + stg*KV_STG;

        // S[rowm:+16][kcol:+32] = Q @ K^T
        wmma::fragment<wmma::accumulator, 16, 16, 8, float> sacc[2];
        #pragma unroll
        for (int j = 0; j < 2; j++) wmma::fill_fragment(sacc[j], 0.f);
        #pragma unroll
        for (int ks = 0; ks < 8; ks++) {
            wmma::fragment<wmma::matrix_a, 16, 16, 8, wmma::precision::tf32, wmma::row_major> aq;
            wmma::load_matrix_sync(aq, Qs + rowm*AP + ks*8, AP);
            #pragma unroll
            for (int j = 0; j < 2; j++) {
                wmma::fragment<wmma::matrix_b, 16, 16, 8, wmma::precision::tf32, wmma::col_major> bk;
                wmma::load_matrix_sync(bk, kc + (kcol + j*16)*AP + ks*8, AP);
                wmma::mma_sync(sacc[j], aq, bk, sacc[j]);
            }
        }

        // P = round_tf32(exp(S)) on registers (elementwise, layout-free)
        #pragma unroll
        for (int j = 0; j < 2; j++) {
            #pragma unroll
            for (int t = 0; t < sacc[j].num_elements; t++)
                sacc[j].x[t] = to_tf32(__expf(sacc[j].x[t]));
            wmma::store_matrix_sync(Ps + rowm*AP + kcol + j*16, sacc[j], AP,
                                    wmma::mem_row_major);
        }
        __syncthreads();   // full P tile visible

        if (kt + 1 < Tn/64) prefetch_kv(kt + 1, stg ^ 1);

        // Row sums (read-only): thread covers row tid>>2, 16 cols
        {
            const int r  = tid >> 2;
            const float* pr = Ps + r*AP + (tid & 3) * 16;
            float s0 = 0.f;
            #pragma unroll
            for (int j = 0; j < 16; j++) s0 += pr[j];
            s0 += __shfl_xor_sync(0xffffffffu, s0, 1);
            s0 += __shfl_xor_sync(0xffffffffu, s0, 2);
            if ((tid & 3) == 0) lrow[r] += s0;
        }

        // O_partial += P[rowm][kcol:+32] @ V[kcol:+32][:]
        #pragma unroll
        for (int ks = 0; ks < 4; ks++) {
            wmma::fragment<wmma::matrix_a, 16, 16, 8, wmma::precision::tf32, wmma::row_major> ap;
            wmma::load_matrix_sync(ap, Ps + rowm*AP + kcol + ks*8, AP);
            #pragma unroll
            for (int j = 0; j < 4; j++) {
                wmma::fragment<wmma::matrix_b, 16, 16, 8, wmma::precision::tf32, wmma::row_major> bv;
                wmma::load_matrix_sync(bv, vc + (kcol + ks*8)*AP + j*16, AP);
                wmma::mma_sync(oacc[j], ap, bv, oacc[j]);
            }
        }
        stg ^= 1;
    }

    // Reduce the two key-half partials (reuse Ks region as scratch)
    __syncthreads();
    float* Op = Ks + kh * KV_STG;
    #pragma unroll
    for (int j = 0; j < 4; j++)
        wmma::store_matrix_sync(Op + rowm*AP + j*16, oacc[j], AP, wmma::mem_row_major);
    __syncthreads();

    {
        const int r  = tid >> 2;
        const int c0 = (tid & 3) * 16;
        const float inv = 1.f / lrow[r];
        const float* p0 = Ks + r*AP + c0;
        const float* p1 = Ks + KV_STG + r*AP + c0;
        float* dst = outp + (size_t)(b*Tn + q0 + r) * Dn + h*HDn + c0;
        #pragma unroll
        for (int j = 0; j < 4; j++) {
            float4 a = *(const float4*)(p0 + j*4);
            float4 c = *(const float4*)(p1 + j*4);
            float4 v;
            v.x = to_tf32((a.x + c.x) * inv);
            v.y = to_tf32((a.y + c.y) * inv);
            v.z = to_tf32((a.z + c.z) * inv);
            v.w = to_tf32((a.w + c.w) * inv);
            *(float4*)(dst + j*4) = v;
        }
    }
}

// ---------------------------------------------------------------------------
extern "C" void kernel_launch(void* const* d_in, const int* in_sizes, int n_in,
                              void* d_out, int out_size)
{
    const float* x    = (const float*)d_in[0];
    const float* Wqkv = (const float*)d_in[1];
    const float* Wo   = (const float*)d_in[2];
    const float* bo   = (const float*)d_in[3];
    float* out = (float*)d_out;

    float *qkv, *att, *xr, *wq, *wo;
    cudaGetSymbolAddress((void**)&qkv, g_qkv);
    cudaGetSymbolAddress((void**)&att, g_attn);
    cudaGetSymbolAddress((void**)&xr,  g_xr);
    cudaGetSymbolAddress((void**)&wq,  g_wq);
    cudaGetSymbolAddress((void**)&wo,  g_wo);

    cudaFuncSetAttribute(gemm_tf32_v3<0>,
                         cudaFuncAttributeMaxDynamicSharedMemorySize, GEMM_SMEM);
    cudaFuncSetAttribute(gemm_tf32_v3<1>,
                         cudaFuncAttributeMaxDynamicSharedMemorySize, GEMM_SMEM);
    cudaFuncSetAttribute(attn_tc_kernel,
                         cudaFuncAttributeMaxDynamicSharedMemorySize, ATT_SMEM);

    // 0) pre-round inputs to tf32
    {
        int n4;
        n4 = MROWS*Dn/4;   preround_kernel<<<(n4+255)/256, 256>>>(x,    xr, n4);
        n4 = Dn*QKVN/4;    preround_kernel<<<(n4+255)/256, 256>>>(Wqkv, wq, n4);
        n4 = Dn*Dn/4;      preround_kernel<<<(n4+255)/256, 256>>>(Wo,   wo, n4);
    }
    // 1) qkv = xr @ wq  (epilogue rounds to tf32)
    {
        dim3 grid(QKVN/128, MROWS/128);
        gemm_tf32_v3<1><<<grid, 256, GEMM_SMEM>>>(xr, wq, qkv, MROWS, QKVN, Dn);
    }
    // 2) RoPE + L2 norm (writes tf32)
    {
        int warps = Bn*Tn*Hn*2;
        rope_norm_kernel<<<warps/8, 256>>>(qkv);
    }
    // 3) attention (writes tf32)
    {
        dim3 grid(Bn * Hn * (Tn/64));   // 2048
        attn_tc_kernel<<<grid, 256, ATT_SMEM>>>(qkv, att);
    }
    // 4) out = att @ wo + bo
    {
        dim3 grid(Dn/128, MROWS/128);
        gemm_tf32_v3<0><<<grid, 256, GEMM_SMEM>>>(att, wo, out, MROWS, Dn, Dn);
        int total4 = MROWS * Dn / 4;
        bias_add_kernel<<<(total4 + 255)/256, 256>>>(out, bo, total4, Dn);
    }
}

// round 9
// speedup vs baseline: 1.0011x; 1.0011x over previous
#include <cuda_runtime.h>
#include <mma.h>
#include <math.h>
#include <stdint.h>

using namespace nvcuda;

#define Bn 4
#define Tn 2048
#define Dn 1024
#define Hn 16
#define HDn 64
#define MROWS (Bn*Tn)      // 8192
#define QKVN (3*Dn)        // 3072

__device__ float g_qkv[(size_t)MROWS * QKVN];
__device__ float g_attn[(size_t)MROWS * Dn];
__device__ float g_xr[(size_t)MROWS * Dn];
__device__ float g_wq[(size_t)Dn * QKVN];
__device__ float g_wo[(size_t)Dn * Dn];

__device__ __forceinline__ float to_tf32(float x) {
    uint32_t u;
    asm("cvt.rna.tf32.f32 %0, %1;" : "=r"(u) : "f"(x));
    return __uint_as_float(u);
}
__device__ __forceinline__ uint32_t s2u(const void* p) {
    return (uint32_t)__cvta_generic_to_shared(p);
}
__device__ __forceinline__ void cp16(uint32_t dst, const void* src) {
    asm volatile("cp.async.cg.shared.global [%0], [%1], 16;" :: "r"(dst), "l"(src));
}
__device__ __forceinline__ void cp_commit() { asm volatile("cp.async.commit_group;"); }
__device__ __forceinline__ void cp_wait0()  { asm volatile("cp.async.wait_group 0;"); }

__global__ void __launch_bounds__(256) preround_kernel(
    const float* __restrict__ src, float* __restrict__ dst, int total4)
{
    int idx = blockIdx.x * blockDim.x + threadIdx.x;
    if (idx >= total4) return;
    float4 v = *(const float4*)&src[idx * 4];
    v.x = to_tf32(v.x); v.y = to_tf32(v.y);
    v.z = to_tf32(v.z); v.w = to_tf32(v.w);
    *(float4*)&dst[idx * 4] = v;
}

// ---------------------------------------------------------------------------
// TF32 GEMM: 128x128 tile, BK=32, cp.async double buffer. Inputs pre-rounded.
// One syncthreads per K-tile (trailing sync is redundant: the top sync after
// cp_wait0 orders all warps' prior-iteration reads before stage overwrite).
// ---------------------------------------------------------------------------
#define AP_A 36
#define AP_B 132
#define A_STG (128*AP_A)
#define B_STG (32*AP_B)
#define GEMM_SMEM ((2*A_STG + 2*B_STG) * 4)

template <int ROUND_OUT>
__global__ void __launch_bounds__(256, 2) gemm_tf32_v3(
    const float* __restrict__ A, const float* __restrict__ Bm,
    float* __restrict__ C, int M, int N, int K)
{
    extern __shared__ float sm[];
    float* As = sm;
    float* Bs = sm + 2*A_STG;

    const int tid = threadIdx.x;
    const int bm = blockIdx.y * 128;
    const int bn = blockIdx.x * 128;
    const int w  = tid >> 5;
    const int wm = (w >> 2) * 64;
    const int wn = (w & 3) * 32;

    wmma::fragment<wmma::accumulator, 16, 16, 8, float> acc[4][2];
    #pragma unroll
    for (int i = 0; i < 4; i++)
        #pragma unroll
        for (int j = 0; j < 2; j++) wmma::fill_fragment(acc[i][j], 0.f);

    const int nk = K / 32;

    auto prefetch = [&](int kt, int stg) {
        const int k0 = kt * 32;
        float* ad = As + stg * A_STG;
        float* bd = Bs + stg * B_STG;
        #pragma unroll
        for (int i = 0; i < 4; i++) {
            int id = tid + 256*i;
            int r = id >> 3, c = (id & 7) * 4;
            cp16(s2u(ad + r*AP_A + c), &A[(size_t)(bm + r) * K + k0 + c]);
        }
        #pragma unroll
        for (int i = 0; i < 4; i++) {
            int id = tid + 256*i;
            int r = id >> 5, c = (id & 31) * 4;
            cp16(s2u(bd + r*AP_B + c), &Bm[(size_t)(k0 + r) * N + bn + c]);
        }
        cp_commit();
    };

    prefetch(0, 0);
    int stg = 0;

    for (int kt = 0; kt < nk; kt++) {
        cp_wait0();
        __syncthreads();
        if (kt + 1 < nk) prefetch(kt + 1, stg ^ 1);

        const float* a0 = As + stg * A_STG;
        const float* b0 = Bs + stg * B_STG;
        #pragma unroll
        for (int kk = 0; kk < 4; kk++) {
            wmma::fragment<wmma::matrix_a, 16, 16, 8, wmma::precision::tf32, wmma::row_major> af[4];
            wmma::fragment<wmma::matrix_b, 16, 16, 8, wmma::precision::tf32, wmma::row_major> bf[2];
            #pragma unroll
            for (int i = 0; i < 4; i++)
                wmma::load_matrix_sync(af[i], a0 + (wm + i*16)*AP_A + kk*8, AP_A);
            #pragma unroll
            for (int j = 0; j < 2; j++)
                wmma::load_matrix_sync(bf[j], b0 + (kk*8)*AP_B + wn + j*16, AP_B);
            #pragma unroll
            for (int i = 0; i < 4; i++)
                #pragma unroll
                for (int j = 0; j < 2; j++)
                    wmma::mma_sync(acc[i][j], af[i], bf[j], acc[i][j]);
        }
        stg ^= 1;
    }

    #pragma unroll
    for (int i = 0; i < 4; i++)
        #pragma unroll
        for (int j = 0; j < 2; j++) {
            if (ROUND_OUT) {
                #pragma unroll
                for (int t = 0; t < acc[i][j].num_elements; t++)
                    acc[i][j].x[t] = to_tf32(acc[i][j].x[t]);
            }
            wmma::store_matrix_sync(&C[(size_t)(bm + wm + i*16) * N + bn + wn + j*16],
                                    acc[i][j], N, wmma::mem_row_major);
        }
}

__global__ void __launch_bounds__(256) bias_add_kernel(
    float* __restrict__ out, const float* __restrict__ bias, int total4, int N)
{
    int idx = blockIdx.x * blockDim.x + threadIdx.x;
    if (idx >= total4) return;
    int col = (idx * 4) & (N - 1);
    float4 v = *(float4*)&out[idx * 4];
    v.x += bias[col+0]; v.y += bias[col+1];
    v.z += bias[col+2]; v.w += bias[col+3];
    *(float4*)&out[idx * 4] = v;
}

// ---------------------------------------------------------------------------
// RoPE + L2 norm, writes tf32-rounded q,k in place.
// ---------------------------------------------------------------------------
__global__ void __launch_bounds__(256) rope_norm_kernel(float* __restrict__ qkv)
{
    const int gw = (blockIdx.x * blockDim.x + threadIdx.x) >> 5;
    const int lane = threadIdx.x & 31;
    const int which = gw & 1;
    const int h = (gw >> 1) & (Hn - 1);
    const int t = (gw >> 5) & (Tn - 1);
    const int b = gw >> 16;

    float* p = qkv + (size_t)(b*Tn + t) * QKVN + which*Dn + h*HDn;

    // 10000^(-lane/32) = exp2(-lane * log2(10000)/32)
    const float inv_freq = exp2f(-(float)lane * (13.287712379549449f / 32.f));
    const float ang = (float)t * inv_freq;
    float s, c;
    sincosf(ang, &s, &c);

    const float x1 = p[lane];
    const float x2 = p[lane + 32];
    const float r1 = x1*c - x2*s;
    const float r2 = x1*s + x2*c;

    float ss = r1*r1 + r2*r2;
    #pragma unroll
    for (int off = 16; off; off >>= 1)
        ss += __shfl_xor_sync(0xffffffffu, ss, off);

    const float inv = rsqrtf(ss + 1e-6f);
    p[lane]      = to_tf32(r1 * inv);
    p[lane + 32] = to_tf32(r2 * inv);
}

// ---------------------------------------------------------------------------
// TF32 flash attention: 64 q-rows / 128 threads / 4 warps, cp.async double-
// buffered K/V. AP=68 (bank stride 4): halves fragment-load bank conflicts
// vs AP=72 (stride 8 -> 4-way). One syncthreads per tile (trailing sync
// redundant). q,k unit vectors -> |score|<=0.125 -> exp without max/rescale.
// ---------------------------------------------------------------------------
#define AP 68
#define KV_STG (64*AP)
#define ATT_SMEM ((64*AP + 2*KV_STG + 2*KV_STG + 64*AP + 64) * 4)

__global__ void __launch_bounds__(128) attn_tc_kernel(
    const float* __restrict__ qkv, float* __restrict__ outp)
{
    extern __shared__ float sm[];
    float* Qs   = sm;
    float* Ks   = Qs + 64*AP;
    float* Vs   = Ks + 2*KV_STG;
    float* Ps   = Vs + 2*KV_STG;
    float* lrow = Ps + 64*AP;

    const int tid  = threadIdx.x;
    const int w    = tid >> 5;
    const int lane = tid & 31;

    const int qt = blockIdx.x & 31;
    const int h  = (blockIdx.x >> 5) & (Hn-1);
    const int b  = blockIdx.x >> 9;
    const int q0 = qt * 64;

    const float* qbase = qkv + (size_t)(b*Tn) * QKVN + h*HDn;
    const float* kbase = qbase + Dn;
    const float* vbase = qbase + 2*Dn;

    auto prefetch_kv = [&](int kt, int stg) {
        float* kd = Ks + stg*KV_STG;
        float* vd = Vs + stg*KV_STG;
        #pragma unroll
        for (int i = 0; i < 8; i++) {
            int id = tid + 128*i;
            int r = id >> 4, c = (id & 15) * 4;
            cp16(s2u(kd + r*AP + c), kbase + (size_t)(kt*64 + r) * QKVN + c);
        }
        #pragma unroll
        for (int i = 0; i < 8; i++) {
            int id = tid + 128*i;
            int r = id >> 4, c = (id & 15) * 4;
            cp16(s2u(vd + r*AP + c), vbase + (size_t)(kt*64 + r) * QKVN + c);
        }
        cp_commit();
    };

    prefetch_kv(0, 0);

    {
        const int r  = tid >> 1;
        const int c0 = (tid & 1) * 32;
        const float* src = qbase + (size_t)(q0 + r) * QKVN + c0;
        float* dst = Qs + r*AP + c0;
        #pragma unroll
        for (int j = 0; j < 8; j++) {
            float4 v = *(const float4*)(src + j*4);
            dst[j*4+0] = 0.125f * v.x;
            dst[j*4+1] = 0.125f * v.y;
            dst[j*4+2] = 0.125f * v.z;
            dst[j*4+3] = 0.125f * v.w;
        }
    }
    if (tid < 64) lrow[tid] = 0.f;

    wmma::fragment<wmma::accumulator, 16, 16, 8, float> oacc[4];
    #pragma unroll
    for (int j = 0; j < 4; j++) wmma::fill_fragment(oacc[j], 0.f);

    const int rowm = w * 16;
    int stg = 0;

    for (int kt = 0; kt < Tn/64; kt++) {
        cp_wait0();
        __syncthreads();   // KV stage ready + all warps completed prior iter
        if (kt + 1 < Tn/64) prefetch_kv(kt + 1, stg ^ 1);

        const float* kc = Ks + stg*KV_STG;
        const float* vc = Vs + stg*KV_STG;

        // S = Q @ K^T
        wmma::fragment<wmma::accumulator, 16, 16, 8, float> sacc[4];
        #pragma unroll
        for (int j = 0; j < 4; j++) wmma::fill_fragment(sacc[j], 0.f);
        #pragma unroll
        for (int ks = 0; ks < 8; ks++) {
            wmma::fragment<wmma::matrix_a, 16, 16, 8, wmma::precision::tf32, wmma::row_major> aq;
            wmma::load_matrix_sync(aq, Qs + rowm*AP + ks*8, AP);
            #pragma unroll
            for (int j = 0; j < 4; j++) {
                wmma::fragment<wmma::matrix_b, 16, 16, 8, wmma::precision::tf32, wmma::col_major> bk;
                wmma::load_matrix_sync(bk, kc + j*16*AP + ks*8, AP);
                wmma::mma_sync(sacc[j], aq, bk, sacc[j]);
            }
        }
        #pragma unroll
        for (int j = 0; j < 4; j++)
            wmma::store_matrix_sync(Ps + rowm*AP + j*16, sacc[j], AP, wmma::mem_row_major);
        __syncwarp();

        // P = exp(S), tf32-rounded; row sums. No max needed.
        {
            const int rr = rowm + (lane >> 1);
            const int cc = (lane & 1) * 32;
            float* pr = Ps + rr*AP + cc;
            float sum = 0.f;
            #pragma unroll
            for (int j = 0; j < 32; j++) {
                float e = __expf(pr[j]);
                sum += e;
                pr[j] = to_tf32(e);
            }
            sum += __shfl_xor_sync(0xffffffffu, sum, 1);
            if (!(lane & 1)) lrow[rr] += sum;
        }
        __syncwarp();

        // O += P @ V
        #pragma unroll
        for (int ks = 0; ks < 8; ks++) {
            wmma::fragment<wmma::matrix_a, 16, 16, 8, wmma::precision::tf32, wmma::row_major> ap;
            wmma::load_matrix_sync(ap, Ps + rowm*AP + ks*8, AP);
            #pragma unroll
            for (int j = 0; j < 4; j++) {
                wmma::fragment<wmma::matrix_b, 16, 16, 8, wmma::precision::tf32, wmma::row_major> bv;
                wmma::load_matrix_sync(bv, vc + ks*8*AP + j*16, AP);
                wmma::mma_sync(oacc[j], ap, bv, oacc[j]);
            }
        }
        stg ^= 1;
    }

    __syncthreads();
    #pragma unroll
    for (int j = 0; j < 4; j++)
        wmma::store_matrix_sync(Ps + rowm*AP + j*16, oacc[j], AP, wmma::mem_row_major);
    __syncthreads();

    {
        const int r  = tid >> 1;
        const int c0 = (tid & 1) * 32;
        const float inv = 1.f / lrow[r];
        const float* srcr = Ps + r*AP + c0;
        float* dst = outp + (size_t)(b*Tn + q0 + r) * Dn + h*HDn + c0;
        #pragma unroll
        for (int j = 0; j < 8; j++) {
            float4 v;
            v.x = to_tf32(srcr[j*4+0] * inv);
            v.y = to_tf32(srcr[j*4+1] * inv);
            v.z = to_tf32(srcr[j*4+2] * inv);
            v.w = to_tf32(srcr[j*4+3] * inv);
            *(float4*)(dst + j*4) = v;
        }
    }
}

// ---------------------------------------------------------------------------
extern "C" void kernel_launch(void* const* d_in, const int* in_sizes, int n_in,
                              void* d_out, int out_size)
{
    const float* x    = (const float*)d_in[0];
    const float* Wqkv = (const float*)d_in[1];
    const float* Wo   = (const float*)d_in[2];
    const float* bo   = (const float*)d_in[3];
    float* out = (float*)d_out;

    float *qkv, *att, *xr, *wq, *wo;
    cudaGetSymbolAddress((void**)&qkv, g_qkv);
    cudaGetSymbolAddress((void**)&att, g_attn);
    cudaGetSymbolAddress((void**)&xr,  g_xr);
    cudaGetSymbolAddress((void**)&wq,  g_wq);
    cudaGetSymbolAddress((void**)&wo,  g_wo);

    cudaFuncSetAttribute(gemm_tf32_v3<0>,
                         cudaFuncAttributeMaxDynamicSharedMemorySize, GEMM_SMEM);
    cudaFuncSetAttribute(gemm_tf32_v3<1>,
                         cudaFuncAttributeMaxDynamicSharedMemorySize, GEMM_SMEM);
    cudaFuncSetAttribute(attn_tc_kernel,
                         cudaFuncAttributeMaxDynamicSharedMemorySize, ATT_SMEM);

    // 0) pre-round inputs to tf32
    {
        int n4;
        n4 = MROWS*Dn/4;   preround_kernel<<<(n4+255)/256, 256>>>(x,    xr, n4);
        n4 = Dn*QKVN/4;    preround_kernel<<<(n4+255)/256, 256>>>(Wqkv, wq, n4);
        n4 = Dn*Dn/4;      preround_kernel<<<(n4+255)/256, 256>>>(Wo,   wo, n4);
    }
    // 1) qkv = xr @ wq  (epilogue rounds to tf32)
    {
        dim3 grid(QKVN/128, MROWS/128);
        gemm_tf32_v3<1><<<grid, 256, GEMM_SMEM>>>(xr, wq, qkv, MROWS, QKVN, Dn);
    }
    // 2) RoPE + L2 norm (writes tf32)
    {
        int warps = Bn*Tn*Hn*2;
        rope_norm_kernel<<<warps/8, 256>>>(qkv);
    }
    // 3) attention (writes tf32)
    {
        dim3 grid(Bn * Hn * (Tn/64));   // 2048
        attn_tc_kernel<<<grid, 128, ATT_SMEM>>>(qkv, att);
    }
    // 4) out = att @ wo + bo
    {
        dim3 grid(Dn/128, MROWS/128);
        gemm_tf32_v3<0><<<grid, 256, GEMM_SMEM>>>(att, wo, out, MROWS, Dn, Dn);
        int total4 = MROWS * Dn / 4;
        bias_add_kernel<<<(total4 + 255)/256, 256>>>(out, bo, total4, Dn);
    }
}